// round 3
// baseline (speedup 1.0000x reference)
#include <cuda_runtime.h>

#define AALPHA 0.42f
#define IMG_H 1024
#define IMG_W 1024
#define NIMG 48     // 16 batches * 3 masks
#define RPW 64      // output rows per warp task
#define STRIPS 8    // 128 columns per strip

__device__ float g_scores[NIMG];
__device__ float g_weights[NIMG];

// fast sigmoid: 1/(1+2^(-x*log2e)), err ~1e-7
__device__ __forceinline__ float fsig(float x) {
    float e;
    asm("ex2.approx.f32 %0, %1;" : "=f"(e) : "f"(-1.4426950408889634f * x));
    float r;
    asm("rcp.approx.f32 %0, %1;" : "=f"(r) : "f"(1.0f + e));
    return r;
}
__device__ __forceinline__ float fsqrt_fast(float x) {
    float r; asm("sqrt.approx.f32 %0, %1;" : "=f"(r) : "f"(x)); return r;
}

__global__ void zero_scores_kernel() {
    if (threadIdx.x < NIMG) g_scores[threadIdx.x] = 0.0f;
}

// ---------------------------------------------------------------------------
// score = ALPHA * sum(edge) + (1-ALPHA)/49 * sum( cnt(p) * (m_p - mean_p)^2 )
//
// Warp-autonomous: each warp owns a 128-col strip x 64 output rows. Lane owns
// 4 cols; +-3 col halo via __shfl lane+-1; strip-edge lanes (0/31) load halo
// float4 from global (predicated). NO __syncthreads. 2-deep LDG prefetch.
// Vertical 7-window sum: 8-deep h-sum register ring. Conv: 4-deep raw m-ring.
// ---------------------------------------------------------------------------
__global__ __launch_bounds__(256, 2) void score_kernel(const float* __restrict__ logits) {
    const int lane = threadIdx.x & 31;
    const int wid  = threadIdx.x >> 5;
    const int task = blockIdx.x * 8 + wid;          // 6144 tasks
    const int img   = task >> 7;                    // 128 tasks per image
    const int rem   = task & 127;
    const int strip = rem & 7;
    const int chunk = rem >> 3;
    const int y0 = chunk * RPW;
    const int x0 = strip * 128;
    const int c0 = x0 + lane * 4;
    const float* base = logits + (size_t)img * (IMG_H * IMG_W);

    const bool pl = (lane == 0)  && (x0 > 0);
    const bool pr = (lane == 31) && (x0 + 128 < IMG_W);

    float cwf[4];
    #pragma unroll
    for (int j = 0; j < 4; ++j) {
        int col = c0 + j;
        cwf[j] = (float)(min(col, 3) + min(IMG_W - 1 - col, 3) + 1);
    }

    float hr[8][4];            // h-sum ring for vertical 7-window
    float A[4][6];             // m-ring: 4 rows x {lm, a0..a3, rm}
    float vs[4] = {0.f, 0.f, 0.f, 0.f};
    #pragma unroll
    for (int k = 0; k < 8; ++k) { hr[k][0]=hr[k][1]=hr[k][2]=hr[k][3]=0.f; }
    #pragma unroll
    for (int k = 0; k < 4; ++k) {
        #pragma unroll
        for (int j = 0; j < 6; ++j) A[k][j] = 0.f;
    }

    // 2-deep prefetch buffers
    float4 bm[2], bl[2], br[2];

    #define LOAD_ROW(slot, I)                                               \
        do {                                                                \
            int gy_ = y0 - 3 + (I);                                         \
            bm[slot] = make_float4(0.f, 0.f, 0.f, 0.f);                     \
            bl[slot] = bm[slot]; br[slot] = bm[slot];                       \
            if ((unsigned)gy_ < IMG_H && (I) < 70) {                        \
                const float* r_ = base + (size_t)gy_ * IMG_W;               \
                bm[slot] = *(const float4*)(r_ + c0);                       \
                if (pl) bl[slot] = *(const float4*)(r_ + c0 - 4);           \
                if (pr) br[slot] = *(const float4*)(r_ + c0 + 4);           \
            }                                                               \
        } while (0)

    LOAD_ROW(0, 0);
    LOAD_ROW(1, 1);

    float acc_e = 0.f, acc_v = 0.f;

    for (int ii = 0; ii < 72; ii += 8) {
        #pragma unroll
        for (int u = 0; u < 8; ++u) {
            const int i  = ii + u;
            const int gy = y0 - 3 + i;
            const bool valid = ((unsigned)gy < IMG_H) && (i < 70);

            // consume buffer, then immediately refill (prefetch i+2)
            const float4 M = bm[u & 1];
            const float4 L = bl[u & 1];
            const float4 R = br[u & 1];
            LOAD_ROW(u & 1, i + 2);

            float m0 = valid ? fsig(M.x) : 0.f;
            float m1 = valid ? fsig(M.y) : 0.f;
            float m2 = valid ? fsig(M.z) : 0.f;
            float m3 = valid ? fsig(M.w) : 0.f;

            // halos via shfl (lane-1's m1..m3 = cols c0-3..c0-1; lane+1's m0..m2)
            float lm1 = __shfl_up_sync(0xffffffffu, m1, 1);
            float lm2 = __shfl_up_sync(0xffffffffu, m2, 1);
            float lm3 = __shfl_up_sync(0xffffffffu, m3, 1);
            float rm0 = __shfl_down_sync(0xffffffffu, m0, 1);
            float rm1 = __shfl_down_sync(0xffffffffu, m1, 1);
            float rm2 = __shfl_down_sync(0xffffffffu, m2, 1);
            if (lane == 0) {
                lm1 = (valid && pl) ? fsig(L.y) : 0.f;
                lm2 = (valid && pl) ? fsig(L.z) : 0.f;
                lm3 = (valid && pl) ? fsig(L.w) : 0.f;
            }
            if (lane == 31) {
                rm0 = (valid && pr) ? fsig(R.x) : 0.f;
                rm1 = (valid && pr) ? fsig(R.y) : 0.f;
                rm2 = (valid && pr) ? fsig(R.z) : 0.f;
            }

            // horizontal 7-sums (cols c0..c0+3)
            float h0 = ((lm1 + lm2) + (lm3 + m0)) + ((m1 + m2) + m3);
            float h1 = h0 - lm1 + rm0;
            float h2 = h1 - lm2 + rm1;
            float h3 = h2 - lm3 + rm2;

            // vertical window slide: + h(row i) - h(row i-7)
            vs[0] += h0 - hr[(u + 1) & 7][0];
            vs[1] += h1 - hr[(u + 1) & 7][1];
            vs[2] += h2 - hr[(u + 1) & 7][2];
            vs[3] += h3 - hr[(u + 1) & 7][3];
            hr[u][0] = h0; hr[u][1] = h1; hr[u][2] = h2; hr[u][3] = h3;

            // output row yo = y0 + i - 6, conv rows i-4 (T), i-3 (M), i-2 (B)
            if (i >= 6 && i < 70) {
                const int yo = y0 + i - 6;
                const float chf = (float)(min(yo, 3) + min(IMG_H - 1 - yo, 3) + 1);
                const int T = u & 3, Mi = (u + 1) & 3, B = (u + 2) & 3;
                float rowv = 0.f;
                #pragma unroll
                for (int j = 0; j < 4; ++j) {
                    float lT = A[T][j],  cT = A[T][j + 1],  rT = A[T][j + 2];
                    float lM = A[Mi][j], cM = A[Mi][j + 1], rM = A[Mi][j + 2];
                    float lB = A[B][j],  cB = A[B][j + 1],  rB = A[B][j + 2];
                    float tT = lT - rT, tM = lM - rM, tB = lB - rB;
                    float gxv = fmaf(2.f, tM, tT + tB);
                    float sT  = fmaf(2.f, cT, lT + rT);
                    float sB  = fmaf(2.f, cB, lB + rB);
                    float gyv = sT - sB;
                    float lap = fmaf(-4.f, cM, (cT + cB) + (lM + rM));
                    acc_e += fsqrt_fast(fmaf(gxv, gxv, gyv * gyv)) + 0.5f * fabsf(lap);
                    float d = fmaf(-(1.f / 49.f), vs[j], cM);
                    rowv += cwf[j] * (d * d);
                }
                acc_v += chf * rowv;
            }

            // store row i into ring slot u&3 (overwrites row i-4, already used)
            A[u & 3][0] = lm3; A[u & 3][1] = m0; A[u & 3][2] = m1;
            A[u & 3][3] = m2;  A[u & 3][4] = m3; A[u & 3][5] = rm0;
        }
    }
    #undef LOAD_ROW

    float acc = AALPHA * acc_e + ((1.0f - AALPHA) / 49.0f) * acc_v;

    // warp reduction + atomic (no block sync needed)
    #pragma unroll
    for (int off = 16; off; off >>= 1)
        acc += __shfl_down_sync(0xffffffffu, acc, off);
    if (lane == 0) atomicAdd(&g_scores[img], acc);
}

// ---------------------------------------------------------------------------
// weights[b,s] = 0.5 * ( score[b,s]/(sum_s score[b,:]+1e-6) + softmax(lw)[s] )
// ---------------------------------------------------------------------------
__global__ void weights_kernel(const float* __restrict__ lw) {
    __shared__ float ss[NIMG];
    __shared__ float soft[3];
    int tid = threadIdx.x;
    if (tid < NIMG) ss[tid] = g_scores[tid];
    if (tid == 0) {
        float a = lw[0], b = lw[1], c = lw[2];
        float m = fmaxf(a, fmaxf(b, c));
        float e0 = expf(a - m), e1 = expf(b - m), e2 = expf(c - m);
        float inv = 1.0f / (e0 + e1 + e2);
        soft[0] = e0 * inv; soft[1] = e1 * inv; soft[2] = e2 * inv;
    }
    __syncthreads();
    if (tid < NIMG) {
        int b = tid / 3;
        int s = tid - b * 3;
        float denom = ss[b * 3] + ss[b * 3 + 1] + ss[b * 3 + 2] + 1e-6f;
        g_weights[tid] = (ss[tid] / denom + soft[s]) * 0.5f;
    }
}

// ---------------------------------------------------------------------------
// fused[b,p] = sum_s logits[b,s,p] * w[b,s]   (float4 vectorized)
// ---------------------------------------------------------------------------
__global__ __launch_bounds__(256) void fuse_kernel(const float* __restrict__ logits,
                                                   float* __restrict__ out) {
    const int N = IMG_H * IMG_W;
    int b = blockIdx.y;
    int i = blockIdx.x * blockDim.x + threadIdx.x;   // over N/4
    float w0 = g_weights[b * 3 + 0];
    float w1 = g_weights[b * 3 + 1];
    float w2 = g_weights[b * 3 + 2];
    const float4* p0 = (const float4*)(logits + (size_t)(b * 3 + 0) * N);
    const float4* p1 = (const float4*)(logits + (size_t)(b * 3 + 1) * N);
    const float4* p2 = (const float4*)(logits + (size_t)(b * 3 + 2) * N);
    float4 a = p0[i], bb = p1[i], cc = p2[i];
    float4 o;
    o.x = a.x * w0 + bb.x * w1 + cc.x * w2;
    o.y = a.y * w0 + bb.y * w1 + cc.y * w2;
    o.z = a.z * w0 + bb.z * w1 + cc.z * w2;
    o.w = a.w * w0 + bb.w * w1 + cc.w * w2;
    ((float4*)out)[(size_t)b * (N / 4) + i] = o;
}

extern "C" void kernel_launch(void* const* d_in, const int* in_sizes, int n_in,
                              void* d_out, int out_size) {
    const float* logits = (const float*)d_in[0];   // (16,3,1024,1024) fp32
    const float* lw     = (const float*)d_in[1];   // (3,) fp32
    float* out          = (float*)d_out;           // (16,1024,1024) fp32

    zero_scores_kernel<<<1, 64>>>();
    score_kernel<<<NIMG * STRIPS * (IMG_H / RPW) / 8, 256>>>(logits);
    weights_kernel<<<1, 64>>>(lw);
    fuse_kernel<<<dim3((IMG_H * IMG_W / 4) / 256, 16), 256>>>(logits, out);
}

// round 4
// speedup vs baseline: 1.6475x; 1.6475x over previous
#include <cuda_runtime.h>

#define AALPHA 0.42f
#define IMG_H 1024
#define IMG_W 1024
#define NIMG 48     // 16 batches * 3 masks
#define RPB 64      // output rows per block
#define BPI 16      // blocks per image (IMG_H / RPB)

__device__ float g_part[NIMG * BPI];
__device__ float g_weights[NIMG];

// fast sigmoid: 1/(1+2^(-x*log2e)), err ~1e-7
__device__ __forceinline__ float fsig(float x) {
    float e;
    asm("ex2.approx.f32 %0, %1;" : "=f"(e) : "f"(-1.4426950408889634f * x));
    float r;
    asm("rcp.approx.f32 %0, %1;" : "=f"(r) : "f"(1.0f + e));
    return r;
}
__device__ __forceinline__ float fsqrt_fast(float x) {
    float r; asm("sqrt.approx.f32 %0, %1;" : "=f"(r) : "f"(x)); return r;
}

// ---------------------------------------------------------------------------
// score = ALPHA * sum(edge) + (1-ALPHA)/49 * sum( cnt(p) * (m_p - mean_p)^2 )
// Full-width rows, 64 output rows/block, vertical register sliding.
// Thread t owns cols 4t..4t+3. Pipeline: LDG(row i+1) issued at top of iter i
// (one full iteration of slack); sigmoid+STS+BAR+consume for row i.
// h-sums slide horizontally in regs; vertical 7-window via 8-deep h-sum ring;
// conv via 4-deep (s,t,c) combo ring. Unroll-8 keeps ring indices static.
// ---------------------------------------------------------------------------
__global__ __launch_bounds__(256, 2) void score_kernel(const float* __restrict__ logits) {
    __shared__ float rowbuf[2][1032];   // cols -4..1027, data at offset 4
    __shared__ float red[8];

    const int img = blockIdx.y;
    const int y0  = blockIdx.x * RPB;
    const int t   = threadIdx.x;
    const int c0  = t * 4;
    const float* base = logits + (size_t)img * (IMG_H * IMG_W);

    // zero pad columns of both buffers (written once, never overwritten)
    if (t < 16) {
        int b = t >> 3, j = t & 7;
        rowbuf[b][(j < 4) ? j : (1020 + j)] = 0.0f;   // j 4..7 -> 1024..1027
    }

    float hr[8][4];                      // horizontal-7-sum ring
    float rs[4][4], rt[4][4], rc[4][4];  // per-row conv combo ring
    float vs[4] = {0.f, 0.f, 0.f, 0.f};
    #pragma unroll
    for (int k = 0; k < 8; ++k) { hr[k][0]=hr[k][1]=hr[k][2]=hr[k][3]=0.f; }
    #pragma unroll
    for (int k = 0; k < 4; ++k) {
        #pragma unroll
        for (int j = 0; j < 4; ++j) { rs[k][j]=0.f; rt[k][j]=0.f; rc[k][j]=0.f; }
    }

    float cwf[4];
    #pragma unroll
    for (int j = 0; j < 4; ++j) {
        int col = c0 + j;
        cwf[j] = (float)(min(col, 3) + min(IMG_W - 1 - col, 3) + 1);
    }

    float acc_e = 0.f, acc_v = 0.f;

    // prefetch row i=0 (gy = y0-3)
    float4 cur = make_float4(0.f, 0.f, 0.f, 0.f);
    {
        int gy = y0 - 3;
        if ((unsigned)gy < IMG_H)
            cur = *(const float4*)(base + (size_t)gy * IMG_W + c0);
    }

    // rows i=0..69 -> gy = y0-3+i ; output row y = gy-3 for i in [6,70)
    for (int ii = 0; ii < 72; ii += 8) {
        #pragma unroll
        for (int u = 0; u < 8; ++u) {
            const int i  = ii + u;
            const int gy = y0 - 3 + i;
            const bool valid = ((unsigned)gy < IMG_H) && (i < 70);

            // 0) prefetch row i+1 (consumed next iteration)
            float4 nxt = make_float4(0.f, 0.f, 0.f, 0.f);
            {
                int gyn = gy + 1;
                if ((unsigned)gyn < IMG_H && (i + 1) < 70)
                    nxt = *(const float4*)(base + (size_t)gyn * IMG_W + c0);
            }

            // 1) sigmoid of current row (zeros outside image)
            float m0 = valid ? fsig(cur.x) : 0.f;
            float m1 = valid ? fsig(cur.y) : 0.f;
            float m2 = valid ? fsig(cur.z) : 0.f;
            float m3 = valid ? fsig(cur.w) : 0.f;
            float* rb = rowbuf[u & 1];
            *(float4*)(rb + 4 + c0) = make_float4(m0, m1, m2, m3);
            __syncthreads();

            // 2) read cols c0-4 .. c0+7 (3 aligned float4)
            const float4 A = *(const float4*)(rb + c0);
            const float4 B = *(const float4*)(rb + c0 + 4);
            const float4 C = *(const float4*)(rb + c0 + 8);

            // horizontal 7-sums for cols c0..c0+3
            float h0 = ((A.y + A.z) + (A.w + B.x)) + ((B.y + B.z) + B.w);
            float h1 = h0 + C.x - A.y;
            float h2 = h1 + C.y - A.z;
            float h3 = h2 + C.z - A.w;

            // vertical window slide: + h(row i) - h(row i-7)
            vs[0] += h0 - hr[(u + 1) & 7][0];
            vs[1] += h1 - hr[(u + 1) & 7][1];
            vs[2] += h2 - hr[(u + 1) & 7][2];
            vs[3] += h3 - hr[(u + 1) & 7][3];
            hr[u][0] = h0; hr[u][1] = h1; hr[u][2] = h2; hr[u][3] = h3;

            // 3) output row y = gy-3 (conv rows from ring: i-4, i-3, i-2)
            if (i >= 6 && i < 70) {
                const int yo = gy - 3;
                const float chf = (float)(min(yo, 3) + min(IMG_H - 1 - yo, 3) + 1);
                const int T = u & 3, M = (u + 1) & 3, Bo = (u + 2) & 3;
                float rowv = 0.f;
                #pragma unroll
                for (int j = 0; j < 4; ++j) {
                    float gxv = fmaf(2.f, rt[M][j], rt[T][j] + rt[Bo][j]);
                    float gyv = rs[T][j] - rs[Bo][j];
                    float lap = fmaf(-6.f, rc[M][j], (rc[T][j] + rc[Bo][j]) + rs[M][j]);
                    acc_e += fsqrt_fast(fmaf(gxv, gxv, gyv * gyv)) + 0.5f * fabsf(lap);
                    float d = fmaf(-(1.f / 49.f), vs[j], rc[M][j]);
                    rowv += cwf[j] * (d * d);
                }
                acc_v += chf * rowv;
            }

            // 4) store conv combos for row i (slot u&3, overwrites row i-4)
            const int W = u & 3;
            rs[W][0] = fmaf(2.f, B.x, A.w + B.y); rt[W][0] = A.w - B.y; rc[W][0] = B.x;
            rs[W][1] = fmaf(2.f, B.y, B.x + B.z); rt[W][1] = B.x - B.z; rc[W][1] = B.y;
            rs[W][2] = fmaf(2.f, B.z, B.y + B.w); rt[W][2] = B.y - B.w; rc[W][2] = B.z;
            rs[W][3] = fmaf(2.f, B.w, B.z + C.x); rt[W][3] = B.z - C.x; rc[W][3] = B.w;

            cur = nxt;
        }
    }

    float acc = AALPHA * acc_e + ((1.0f - AALPHA) / 49.0f) * acc_v;

    // block reduction -> per-block partial (no atomics, no zero pass)
    #pragma unroll
    for (int off = 16; off; off >>= 1)
        acc += __shfl_down_sync(0xffffffffu, acc, off);
    if ((t & 31) == 0) red[t >> 5] = acc;
    __syncthreads();
    if (t < 8) {
        float v = red[t];
        #pragma unroll
        for (int off = 4; off; off >>= 1)
            v += __shfl_down_sync(0xffu, v, off);
        if (t == 0) g_part[img * BPI + blockIdx.x] = v;
    }
}

// ---------------------------------------------------------------------------
// reduce partials; weights[b,s] = 0.5*(score/(sum+1e-6) + softmax(lw)[s])
// ---------------------------------------------------------------------------
__global__ void weights_kernel(const float* __restrict__ lw) {
    __shared__ float ss[NIMG];
    __shared__ float soft[3];
    int tid = threadIdx.x;
    if (tid < NIMG) {
        float s = 0.f;
        #pragma unroll
        for (int k = 0; k < BPI; ++k) s += g_part[tid * BPI + k];
        ss[tid] = s;
    }
    if (tid == 0) {
        float a = lw[0], b = lw[1], c = lw[2];
        float m = fmaxf(a, fmaxf(b, c));
        float e0 = expf(a - m), e1 = expf(b - m), e2 = expf(c - m);
        float inv = 1.0f / (e0 + e1 + e2);
        soft[0] = e0 * inv; soft[1] = e1 * inv; soft[2] = e2 * inv;
    }
    __syncthreads();
    if (tid < NIMG) {
        int b = tid / 3;
        int s = tid - b * 3;
        float denom = ss[b * 3] + ss[b * 3 + 1] + ss[b * 3 + 2] + 1e-6f;
        g_weights[tid] = (ss[tid] / denom + soft[s]) * 0.5f;
    }
}

// ---------------------------------------------------------------------------
// fused[b,p] = sum_s logits[b,s,p] * w[b,s]   (float4 vectorized)
// ---------------------------------------------------------------------------
__global__ __launch_bounds__(256) void fuse_kernel(const float* __restrict__ logits,
                                                   float* __restrict__ out) {
    const int N = IMG_H * IMG_W;
    int b = blockIdx.y;
    int i = blockIdx.x * blockDim.x + threadIdx.x;   // over N/4
    float w0 = g_weights[b * 3 + 0];
    float w1 = g_weights[b * 3 + 1];
    float w2 = g_weights[b * 3 + 2];
    const float4* p0 = (const float4*)(logits + (size_t)(b * 3 + 0) * N);
    const float4* p1 = (const float4*)(logits + (size_t)(b * 3 + 1) * N);
    const float4* p2 = (const float4*)(logits + (size_t)(b * 3 + 2) * N);
    float4 a = p0[i], bb = p1[i], cc = p2[i];
    float4 o;
    o.x = a.x * w0 + bb.x * w1 + cc.x * w2;
    o.y = a.y * w0 + bb.y * w1 + cc.y * w2;
    o.z = a.z * w0 + bb.z * w1 + cc.z * w2;
    o.w = a.w * w0 + bb.w * w1 + cc.w * w2;
    ((float4*)out)[(size_t)b * (N / 4) + i] = o;
}

extern "C" void kernel_launch(void* const* d_in, const int* in_sizes, int n_in,
                              void* d_out, int out_size) {
    const float* logits = (const float*)d_in[0];   // (16,3,1024,1024) fp32
    const float* lw     = (const float*)d_in[1];   // (3,) fp32
    float* out          = (float*)d_out;           // (16,1024,1024) fp32

    score_kernel<<<dim3(BPI, NIMG), 256>>>(logits);
    weights_kernel<<<1, 64>>>(lw);
    fuse_kernel<<<dim3((IMG_H * IMG_W / 4) / 256, 16), 256>>>(logits, out);
}

// round 5
// speedup vs baseline: 2.0435x; 1.2403x over previous
#include <cuda_runtime.h>

#define AALPHA 0.42f
#define IMG_H 1024
#define IMG_W 1024
#define NIMG 48     // 16 batches * 3 masks
#define RPB 64      // output rows per block
#define BPI 16      // blocks per image (IMG_H / RPB)

__device__ float g_part[NIMG * BPI];
__device__ float g_weights[NIMG];

// sigmoid(x) = 0.5*tanh(x/2)+0.5  (1 MUFU + 2 fma)
__device__ __forceinline__ float fsig(float x) {
    float t;
    asm("tanh.approx.f32 %0, %1;" : "=f"(t) : "f"(0.5f * x));
    return fmaf(0.5f, t, 0.5f);
}
__device__ __forceinline__ float fsqrt_fast(float x) {
    float r; asm("sqrt.approx.f32 %0, %1;" : "=f"(r) : "f"(x)); return r;
}

// ---------------------------------------------------------------------------
// score = ALPHA * sum(edge) + (1-ALPHA)/49 * sum( cnt(p) * (m_p - mean_p)^2 )
// Full-width rows, 64 output rows/block. Thread t owns cols 4t..4t+3.
// 1-row LDG prefetch; interior blocks (1..14) take a fully static clean path
// (no bounds checks, chf=7 folded out); blocks 0/15 take the guarded path.
// ---------------------------------------------------------------------------
__global__ __launch_bounds__(256, 2) void score_kernel(const float* __restrict__ logits) {
    __shared__ float rowbuf[2][1032];   // cols -4..1027, data at offset 4
    __shared__ float red[8];

    const int img = blockIdx.y;
    const int y0  = blockIdx.x * RPB;
    const int t   = threadIdx.x;
    const int c0  = t * 4;
    const float* base = logits + (size_t)img * (IMG_H * IMG_W);

    // zero pad columns of both buffers (written once)
    if (t < 16) {
        int b = t >> 3, j = t & 7;
        rowbuf[b][(j < 4) ? j : (1020 + j)] = 0.0f;
    }

    float hr[8][4];                      // horizontal-7-sum ring
    float rs[4][4], rt[4][4], rc[4][4];  // conv combo ring
    float vs[4] = {0.f, 0.f, 0.f, 0.f};
    #pragma unroll
    for (int k = 0; k < 8; ++k) { hr[k][0]=hr[k][1]=hr[k][2]=hr[k][3]=0.f; }
    #pragma unroll
    for (int k = 0; k < 4; ++k) {
        #pragma unroll
        for (int j = 0; j < 4; ++j) { rs[k][j]=0.f; rt[k][j]=0.f; rc[k][j]=0.f; }
    }

    float cwf[4];
    #pragma unroll
    for (int j = 0; j < 4; ++j) {
        int col = c0 + j;
        cwf[j] = (float)(min(col, 3) + min(IMG_W - 1 - col, 3) + 1);
    }

    float acc_e = 0.f, acc_v = 0.f, acc;

// per-row body; U, DOOUT, DOPREF are literals -> fully static
#define ROW_BODY(U, DOOUT, DOPREF)                                          \
    do {                                                                    \
        float4 nxt = make_float4(0.f, 0.f, 0.f, 0.f);                       \
        if (DOPREF) { nxt = *(const float4*)rp; rp += IMG_W; }              \
        float m0 = fsig(cur.x), m1 = fsig(cur.y);                           \
        float m2 = fsig(cur.z), m3 = fsig(cur.w);                           \
        float* rb = rowbuf[(U) & 1];                                        \
        *(float4*)(rb + 4 + c0) = make_float4(m0, m1, m2, m3);              \
        __syncthreads();                                                    \
        const float4 A = *(const float4*)(rb + c0);                         \
        const float4 B = *(const float4*)(rb + c0 + 4);                     \
        const float4 C = *(const float4*)(rb + c0 + 8);                     \
        float h0 = ((A.y + A.z) + (A.w + B.x)) + ((B.y + B.z) + B.w);       \
        float h1 = h0 + C.x - A.y;                                          \
        float h2 = h1 + C.y - A.z;                                          \
        float h3 = h2 + C.z - A.w;                                          \
        vs[0] += h0 - hr[((U) + 1) & 7][0];                                 \
        vs[1] += h1 - hr[((U) + 1) & 7][1];                                 \
        vs[2] += h2 - hr[((U) + 1) & 7][2];                                 \
        vs[3] += h3 - hr[((U) + 1) & 7][3];                                 \
        hr[(U) & 7][0] = h0; hr[(U) & 7][1] = h1;                           \
        hr[(U) & 7][2] = h2; hr[(U) & 7][3] = h3;                           \
        if (DOOUT) {                                                        \
            const int T = (U) & 3, M = ((U) + 1) & 3, Bo = ((U) + 2) & 3;   \
            float rowv = 0.f;                                               \
            _Pragma("unroll")                                               \
            for (int j = 0; j < 4; ++j) {                                   \
                float gxv = fmaf(2.f, rt[M][j], rt[T][j] + rt[Bo][j]);      \
                float gyv = rs[T][j] - rs[Bo][j];                           \
                float lap = fmaf(-6.f, rc[M][j],                            \
                                 (rc[T][j] + rc[Bo][j]) + rs[M][j]);        \
                acc_e += fsqrt_fast(fmaf(gxv, gxv, gyv * gyv))              \
                         + 0.5f * fabsf(lap);                               \
                float d = fmaf(-(1.f / 49.f), vs[j], rc[M][j]);             \
                rowv = fmaf(d * cwf[j], d, rowv);                           \
            }                                                               \
            acc_v += rowv;                                                  \
        }                                                                   \
        const int W = (U) & 3;                                              \
        rs[W][0] = fmaf(2.f, B.x, A.w + B.y); rt[W][0] = A.w - B.y; rc[W][0] = B.x; \
        rs[W][1] = fmaf(2.f, B.y, B.x + B.z); rt[W][1] = B.x - B.z; rc[W][1] = B.y; \
        rs[W][2] = fmaf(2.f, B.z, B.y + B.w); rt[W][2] = B.y - B.w; rc[W][2] = B.z; \
        rs[W][3] = fmaf(2.f, B.w, B.z + C.x); rt[W][3] = B.z - C.x; rc[W][3] = B.w; \
        cur = nxt;                                                          \
    } while (0)

    if (blockIdx.x >= 1 && blockIdx.x <= 14) {
        // ---------------- clean path: all rows in-bounds, chf = 7 ----------
        const float* rp = base + (size_t)(y0 - 3) * IMG_W + c0;
        float4 cur = *(const float4*)rp; rp += IMG_W;   // row i=0

        // prologue rows 0..7 (output only rows 6,7)
        ROW_BODY(0, false, true); ROW_BODY(1, false, true);
        ROW_BODY(2, false, true); ROW_BODY(3, false, true);
        ROW_BODY(4, false, true); ROW_BODY(5, false, true);
        ROW_BODY(6, true,  true); ROW_BODY(7, true,  true);

        // middle rows 8..63
        for (int ii = 8; ii < 64; ii += 8) {
            ROW_BODY(0, true, true); ROW_BODY(1, true, true);
            ROW_BODY(2, true, true); ROW_BODY(3, true, true);
            ROW_BODY(4, true, true); ROW_BODY(5, true, true);
            ROW_BODY(6, true, true); ROW_BODY(7, true, true);
        }

        // tail rows 64..69 (last prefetch at row 68)
        ROW_BODY(0, true, true); ROW_BODY(1, true, true);
        ROW_BODY(2, true, true); ROW_BODY(3, true, true);
        ROW_BODY(4, true, true); ROW_BODY(5, true, false);

        acc = AALPHA * acc_e + ((1.0f - AALPHA) / 49.0f) * 7.0f * acc_v;
    } else {
        // ---------------- guarded path (blocks 0 and 15) -------------------
        float4 cur = make_float4(0.f, 0.f, 0.f, 0.f);
        {
            int gy = y0 - 3;
            if ((unsigned)gy < IMG_H)
                cur = *(const float4*)(base + (size_t)gy * IMG_W + c0);
        }
        for (int ii = 0; ii < 72; ii += 8) {
            #pragma unroll
            for (int u = 0; u < 8; ++u) {
                const int i  = ii + u;
                const int gy = y0 - 3 + i;
                const bool valid = ((unsigned)gy < IMG_H) && (i < 70);

                float4 nxt = make_float4(0.f, 0.f, 0.f, 0.f);
                {
                    int gyn = gy + 1;
                    if ((unsigned)gyn < IMG_H && (i + 1) < 70)
                        nxt = *(const float4*)(base + (size_t)gyn * IMG_W + c0);
                }
                float m0 = valid ? fsig(cur.x) : 0.f;
                float m1 = valid ? fsig(cur.y) : 0.f;
                float m2 = valid ? fsig(cur.z) : 0.f;
                float m3 = valid ? fsig(cur.w) : 0.f;
                float* rb = rowbuf[u & 1];
                *(float4*)(rb + 4 + c0) = make_float4(m0, m1, m2, m3);
                __syncthreads();

                const float4 A = *(const float4*)(rb + c0);
                const float4 B = *(const float4*)(rb + c0 + 4);
                const float4 C = *(const float4*)(rb + c0 + 8);

                float h0 = ((A.y + A.z) + (A.w + B.x)) + ((B.y + B.z) + B.w);
                float h1 = h0 + C.x - A.y;
                float h2 = h1 + C.y - A.z;
                float h3 = h2 + C.z - A.w;

                vs[0] += h0 - hr[(u + 1) & 7][0];
                vs[1] += h1 - hr[(u + 1) & 7][1];
                vs[2] += h2 - hr[(u + 1) & 7][2];
                vs[3] += h3 - hr[(u + 1) & 7][3];
                hr[u][0] = h0; hr[u][1] = h1; hr[u][2] = h2; hr[u][3] = h3;

                if (i >= 6 && i < 70) {
                    const int yo = gy - 3;
                    const float chf = (float)(min(yo, 3) + min(IMG_H - 1 - yo, 3) + 1);
                    const int T = u & 3, M = (u + 1) & 3, Bo = (u + 2) & 3;
                    float rowv = 0.f;
                    #pragma unroll
                    for (int j = 0; j < 4; ++j) {
                        float gxv = fmaf(2.f, rt[M][j], rt[T][j] + rt[Bo][j]);
                        float gyv = rs[T][j] - rs[Bo][j];
                        float lap = fmaf(-6.f, rc[M][j], (rc[T][j] + rc[Bo][j]) + rs[M][j]);
                        acc_e += fsqrt_fast(fmaf(gxv, gxv, gyv * gyv)) + 0.5f * fabsf(lap);
                        float d = fmaf(-(1.f / 49.f), vs[j], rc[M][j]);
                        rowv = fmaf(d * cwf[j], d, rowv);
                    }
                    acc_v += chf * rowv;
                }

                const int W = u & 3;
                rs[W][0] = fmaf(2.f, B.x, A.w + B.y); rt[W][0] = A.w - B.y; rc[W][0] = B.x;
                rs[W][1] = fmaf(2.f, B.y, B.x + B.z); rt[W][1] = B.x - B.z; rc[W][1] = B.y;
                rs[W][2] = fmaf(2.f, B.z, B.y + B.w); rt[W][2] = B.y - B.w; rc[W][2] = B.z;
                rs[W][3] = fmaf(2.f, B.w, B.z + C.x); rt[W][3] = B.z - C.x; rc[W][3] = B.w;

                cur = nxt;
            }
        }
        acc = AALPHA * acc_e + ((1.0f - AALPHA) / 49.0f) * acc_v;
    }
#undef ROW_BODY

    // block reduction -> per-block partial
    #pragma unroll
    for (int off = 16; off; off >>= 1)
        acc += __shfl_down_sync(0xffffffffu, acc, off);
    if ((t & 31) == 0) red[t >> 5] = acc;
    __syncthreads();
    if (t < 8) {
        float v = red[t];
        #pragma unroll
        for (int off = 4; off; off >>= 1)
            v += __shfl_down_sync(0xffu, v, off);
        if (t == 0) g_part[img * BPI + blockIdx.x] = v;
    }
}

// ---------------------------------------------------------------------------
// reduce partials; weights[b,s] = 0.5*(score/(sum+1e-6) + softmax(lw)[s])
// ---------------------------------------------------------------------------
__global__ void weights_kernel(const float* __restrict__ lw) {
    __shared__ float ss[NIMG];
    __shared__ float soft[3];
    int tid = threadIdx.x;
    if (tid < NIMG) {
        float s = 0.f;
        #pragma unroll
        for (int k = 0; k < BPI; ++k) s += g_part[tid * BPI + k];
        ss[tid] = s;
    }
    if (tid == 0) {
        float a = lw[0], b = lw[1], c = lw[2];
        float m = fmaxf(a, fmaxf(b, c));
        float e0 = expf(a - m), e1 = expf(b - m), e2 = expf(c - m);
        float inv = 1.0f / (e0 + e1 + e2);
        soft[0] = e0 * inv; soft[1] = e1 * inv; soft[2] = e2 * inv;
    }
    __syncthreads();
    if (tid < NIMG) {
        int b = tid / 3;
        int s = tid - b * 3;
        float denom = ss[b * 3] + ss[b * 3 + 1] + ss[b * 3 + 2] + 1e-6f;
        g_weights[tid] = (ss[tid] / denom + soft[s]) * 0.5f;
    }
}

// ---------------------------------------------------------------------------
// fused[b,p] = sum_s logits[b,s,p] * w[b,s]   (float4 vectorized)
// ---------------------------------------------------------------------------
__global__ __launch_bounds__(256) void fuse_kernel(const float* __restrict__ logits,
                                                   float* __restrict__ out) {
    const int N = IMG_H * IMG_W;
    int b = blockIdx.y;
    int i = blockIdx.x * blockDim.x + threadIdx.x;   // over N/4
    float w0 = g_weights[b * 3 + 0];
    float w1 = g_weights[b * 3 + 1];
    float w2 = g_weights[b * 3 + 2];
    const float4* p0 = (const float4*)(logits + (size_t)(b * 3 + 0) * N);
    const float4* p1 = (const float4*)(logits + (size_t)(b * 3 + 1) * N);
    const float4* p2 = (const float4*)(logits + (size_t)(b * 3 + 2) * N);
    float4 a = p0[i], bb = p1[i], cc = p2[i];
    float4 o;
    o.x = a.x * w0 + bb.x * w1 + cc.x * w2;
    o.y = a.y * w0 + bb.y * w1 + cc.y * w2;
    o.z = a.z * w0 + bb.z * w1 + cc.z * w2;
    o.w = a.w * w0 + bb.w * w1 + cc.w * w2;
    ((float4*)out)[(size_t)b * (N / 4) + i] = o;
}

extern "C" void kernel_launch(void* const* d_in, const int* in_sizes, int n_in,
                              void* d_out, int out_size) {
    const float* logits = (const float*)d_in[0];   // (16,3,1024,1024) fp32
    const float* lw     = (const float*)d_in[1];   // (3,) fp32
    float* out          = (float*)d_out;           // (16,1024,1024) fp32

    score_kernel<<<dim3(BPI, NIMG), 256>>>(logits);
    weights_kernel<<<1, 64>>>(lw);
    fuse_kernel<<<dim3((IMG_H * IMG_W / 4) / 256, 16), 256>>>(logits, out);
}